// round 4
// baseline (speedup 1.0000x reference)
#include <cuda_runtime.h>
#include <math.h>

// ---------------------------------------------------------------------------
// resCNN: 3 locally-connected conv layers (kernel==stride, disjoint patches)
//         + tanh, then Linear(514,2) + softmax. B = 4096.
//
// Layout strategy: transpose x once to [CHW, B] (batch fastest). All
// intermediates stored [Cout, i, j, B]. Every LC layer then becomes, per
// output location, a GEMM  [B x K] * [K x Cout]  with coalesced A loads.
// Compute uses packed fma.rn.f32x2 (2 samples per 64-bit reg) to reach the
// full 128 FMA/cyc/SM fp32 rate on sm_103a.
// ---------------------------------------------------------------------------

#define BATCH 4096

using u64 = unsigned long long;

// Scratch (device globals — no allocations allowed in kernel_launch)
__device__ float g_xT[21600u * BATCH];           // [6*60*60, B]   354 MB
__device__ float g_h0[32u * 20 * 20 * BATCH];    // [32,20,20,B]   210 MB
__device__ float g_h1[64u * 10 * 10 * BATCH];    // [64,10,10,B]   105 MB
__device__ float g_h2[512u * BATCH];             // [512, B]       8.4 MB

__device__ __forceinline__ u64 ffma2(u64 a, u64 b, u64 c) {
    u64 d;
    asm("fma.rn.f32x2 %0, %1, %2, %3;" : "=l"(d) : "l"(a), "l"(b), "l"(c));
    return d;
}

// ------------------------- transpose: [B,CHW] -> [CHW,B] -------------------
__global__ void transpose_kernel(const float* __restrict__ in,
                                 float* __restrict__ out) {
    __shared__ float tile[32][33];
    const int bx = blockIdx.x * 32;   // chw base
    const int by = blockIdx.y * 32;   // batch base
    const int tx = threadIdx.x;       // 0..31
    const int ty = threadIdx.y;       // 0..7
    #pragma unroll
    for (int r = 0; r < 32; r += 8)
        tile[ty + r][tx] = in[(size_t)(by + ty + r) * 21600 + (bx + tx)];
    __syncthreads();
    #pragma unroll
    for (int r = 0; r < 32; r += 8)
        out[(size_t)(bx + ty + r) * BATCH + (by + tx)] = tile[tx][ty + r];
}

// ------------------------- locally connected layer -------------------------
// Per location (li,lj): Out[o,li,lj,b] = tanh( sum_m A[row(m),b]*W[o,m] + bias )
// A is [CIN*HIN*HIN, B]; W is [HOUT*HOUT, COUT, K]; bias [HOUT*HOUT, COUT].
// Block: one location x SAMPLES batch x COUT_TILE outputs.
// Thread tile: TMP sample-pairs (f32x2) x TN outputs.
template<int CIN, int HIN, int KH, int KW, int COUT, int HOUT,
         int COUT_TILE, int SAMPLES, int TMP, int TN, int KT>
__global__ void __launch_bounds__(256)
lc_layer(const float* __restrict__ A, const float* __restrict__ Wt,
         const float* __restrict__ bias, float* __restrict__ Out)
{
    constexpr int K     = CIN * KH * KW;
    constexpr int PAIRS = SAMPLES / 2;
    constexpr int PG    = PAIRS / TMP;       // pair groups (threads along batch)
    constexpr int OG    = COUT_TILE / TN;    // output groups
    static_assert(PG * OG == 256, "thread decomposition");
    static_assert(K % KT == 0, "K tiling");

    const int loc   = blockIdx.y;
    const int li    = loc / HOUT;
    const int lj    = loc % HOUT;
    const int b0    = blockIdx.x * SAMPLES;
    const int obase = blockIdx.z * COUT_TILE;

    __shared__ __align__(16) float sA[KT][SAMPLES];
    __shared__ __align__(16) u64   sW[KT][COUT_TILE];   // duplicated {w,w}

    const int tid = threadIdx.x;
    const int tpx = tid % PG;
    const int tpy = tid / PG;

    u64 acc[TMP][TN];
    #pragma unroll
    for (int m = 0; m < TMP; m++)
        #pragma unroll
        for (int n = 0; n < TN; n++) acc[m][n] = 0ull;

    const float* Wloc = Wt + ((size_t)loc * COUT + obase) * K;

    for (int kt = 0; kt < K; kt += KT) {
        // --- stage A tile (coalesced float4 loads, b-fastest layout) ---
        for (int idx = tid; idx < KT * SAMPLES / 4; idx += 256) {
            const int kk = idx / (SAMPLES / 4);
            const int s4 = idx % (SAMPLES / 4);
            const int m  = kt + kk;
            const int c  = m / (KH * KW);
            const int rm = m % (KH * KW);
            const int r  = rm / KW;
            const int l  = rm % KW;
            const int row = (c * HIN + li * KH + r) * HIN + (lj * KW + l);
            *(float4*)&sA[kk][s4 * 4] =
                *(const float4*)(A + (size_t)row * BATCH + b0 + s4 * 4);
        }
        // --- stage W tile, duplicated into both f32x2 lanes ---
        for (int idx = tid; idx < KT * COUT_TILE; idx += 256) {
            const int kk = idx / COUT_TILE;
            const int o  = idx % COUT_TILE;
            const unsigned int wb =
                __float_as_uint(Wloc[(size_t)o * K + kt + kk]);
            sW[kk][o] = ((u64)wb << 32) | (u64)wb;
        }
        __syncthreads();

        #pragma unroll
        for (int kk = 0; kk < KT; kk++) {
            const u64* sa = (const u64*)sA[kk];
            u64 a[TMP];
            #pragma unroll
            for (int m = 0; m < TMP; m++) a[m] = sa[tpx + m * PG];
            u64 w[TN];
            #pragma unroll
            for (int n = 0; n < TN; n += 2) {
                ulonglong2 wp = *(const ulonglong2*)&sW[kk][tpy * TN + n];
                w[n] = wp.x; w[n + 1] = wp.y;
            }
            #pragma unroll
            for (int m = 0; m < TMP; m++)
                #pragma unroll
                for (int n = 0; n < TN; n++)
                    acc[m][n] = ffma2(a[m], w[n], acc[m][n]);
        }
        __syncthreads();
    }

    // --- epilogue: bias + tanh, store [o, li, lj, b] ---
    #pragma unroll
    for (int n = 0; n < TN; n++) {
        const int o = obase + tpy * TN + n;
        const float bv = bias[loc * COUT + o];
        const size_t outrow = (((size_t)o * HOUT + li) * HOUT + lj) * BATCH + b0;
        #pragma unroll
        for (int m = 0; m < TMP; m++) {
            float2 v;
            v.x = tanhf(__uint_as_float((unsigned)(acc[m][n] & 0xffffffffu)) + bv);
            v.y = tanhf(__uint_as_float((unsigned)(acc[m][n] >> 32)) + bv);
            *(float2*)&Out[outrow + (size_t)(tpx + m * PG) * 2] = v;
        }
    }
}

// ------------------------- classifier + softmax ----------------------------
__global__ void __launch_bounds__(256)
classifier_kernel(const float* __restrict__ h2,    // [512, B]
                  const float* __restrict__ info,  // [B, 2]
                  const float* __restrict__ Wc,    // [514, 2]
                  const float* __restrict__ bc,    // [2]
                  float* __restrict__ out)         // [B, 2]
{
    __shared__ float sW[514 * 2];
    const int tid = threadIdx.x;
    for (int i = tid; i < 514 * 2; i += 256) sW[i] = Wc[i];
    __syncthreads();

    const int b = blockIdx.x * 256 + tid;
    float l0 = bc[0], l1 = bc[1];
    #pragma unroll 8
    for (int f = 0; f < 512; f++) {
        const float v = h2[(size_t)f * BATCH + b];
        l0 = fmaf(v, sW[f * 2 + 0], l0);
        l1 = fmaf(v, sW[f * 2 + 1], l1);
    }
    const float2 iv = *(const float2*)(info + (size_t)b * 2);
    l0 = fmaf(iv.x, sW[512 * 2 + 0], fmaf(iv.y, sW[513 * 2 + 0], l0));
    l1 = fmaf(iv.x, sW[512 * 2 + 1], fmaf(iv.y, sW[513 * 2 + 1], l1));

    const float mx = fmaxf(l0, l1);
    const float e0 = __expf(l0 - mx);   // |arg| <= O(1); fast exp is plenty
    const float e1 = __expf(l1 - mx);
    const float inv = 1.0f / (e0 + e1);
    float2 o = make_float2(e0 * inv, e1 * inv);
    *(float2*)(out + (size_t)b * 2) = o;
}

// ---------------------------------------------------------------------------
extern "C" void kernel_launch(void* const* d_in, const int* in_sizes, int n_in,
                              void* d_out, int out_size) {
    const float* x    = (const float*)d_in[0];
    const float* info = (const float*)d_in[1];
    const float* W0   = (const float*)d_in[2];
    const float* B0   = (const float*)d_in[3];
    const float* W1   = (const float*)d_in[4];
    const float* B1   = (const float*)d_in[5];
    const float* W2   = (const float*)d_in[6];
    const float* B2   = (const float*)d_in[7];
    const float* Wc   = (const float*)d_in[8];
    const float* bc   = (const float*)d_in[9];
    float* out = (float*)d_out;

    float *xT, *h0, *h1, *h2;
    cudaGetSymbolAddress((void**)&xT, g_xT);
    cudaGetSymbolAddress((void**)&h0, g_h0);
    cudaGetSymbolAddress((void**)&h1, g_h1);
    cudaGetSymbolAddress((void**)&h2, g_h2);

    // 1) x [B,21600] -> xT [21600,B]
    transpose_kernel<<<dim3(21600 / 32, BATCH / 32), dim3(32, 8)>>>(x, xT);

    // 2) L0: 6x60x60 -> 32x20x20, k=3 (K=54).  400 locations.
    lc_layer<6, 60, 3, 3, 32, 20,  32, 256, 4, 4,  9>
        <<<dim3(BATCH / 256, 400, 1), 256>>>(xT, W0, B0, h0);

    // 3) L1: 32x20x20 -> 64x10x10, k=2 (K=128). 100 locations.
    lc_layer<32, 20, 2, 2, 64, 10,  64, 256, 4, 8, 16>
        <<<dim3(BATCH / 256, 100, 1), 256>>>(h0, W1, B1, h1);

    // 4) L2: 64x10x10 -> 128x2x2, k=5 (K=1600). 4 locations, Cout split x2.
    lc_layer<64, 10, 5, 5, 128, 2,  64, 128, 4, 4, 16>
        <<<dim3(BATCH / 128, 4, 2), 256>>>(h1, W2, B2, h2);

    // 5) classifier + softmax
    classifier_kernel<<<BATCH / 256, 256>>>(h2, info, Wc, bc, out);
}

// round 5
// speedup vs baseline: 1.0744x; 1.0744x over previous
#include <cuda_runtime.h>
#include <math.h>

// ---------------------------------------------------------------------------
// resCNN: 3 locally-connected conv layers (kernel==stride) + tanh,
//         Linear(514,2) + softmax. B = 4096.
//
// Layout: x transposed once to [CHW, B]; intermediates [Cout,i,j,B].
// Each LC layer = per-location GEMM [B x K] x [K x Cout], fp32 with packed
// fma.rn.f32x2 (2 samples / 64-bit reg) at 128 FMA/cyc/SM.
// Micro-tile 4 sample-pairs x 8 outputs per thread: 32 ffma2 per k-step vs
// ~1.1KB smem traffic/warp -> fma-pipe bound (prev version was LDS-bound 2:1).
// ---------------------------------------------------------------------------

#define BATCH 4096

using u64 = unsigned long long;

// Scratch (device globals — no allocations allowed in kernel_launch)
__device__ float g_xT[21600u * BATCH];           // [6*60*60, B]
__device__ float g_h0[32u * 20 * 20 * BATCH];    // [32,20,20,B]
__device__ float g_h1[64u * 10 * 10 * BATCH];    // [64,10,10,B]
__device__ float g_h2[512u * BATCH];             // [512, B]

__device__ __forceinline__ u64 ffma2(u64 a, u64 b, u64 c) {
    u64 d;
    asm("fma.rn.f32x2 %0, %1, %2, %3;" : "=l"(d) : "l"(a), "l"(b), "l"(c));
    return d;
}

// tanh(x) = 1 - 2/(exp(2x)+1); MUFU.EX2 + MUFU.RCP path, abs err ~1e-7.
__device__ __forceinline__ float tanh_fast(float x) {
    float e = __expf(2.0f * x);
    return 1.0f - __fdividef(2.0f, e + 1.0f);
}

// ------------------------- transpose: [B,CHW] -> [CHW,B] -------------------
__global__ void transpose_kernel(const float* __restrict__ in,
                                 float* __restrict__ out) {
    __shared__ float tile[32][33];
    const int bx = blockIdx.x * 32;   // chw base
    const int by = blockIdx.y * 32;   // batch base
    const int tx = threadIdx.x;
    const int ty = threadIdx.y;
    #pragma unroll
    for (int r = 0; r < 32; r += 8)
        tile[ty + r][tx] = in[(size_t)(by + ty + r) * 21600 + (bx + tx)];
    __syncthreads();
    #pragma unroll
    for (int r = 0; r < 32; r += 8)
        out[(size_t)(bx + ty + r) * BATCH + (by + tx)] = tile[tx][ty + r];
}

// ------------------------- locally connected layer -------------------------
// Out[o,li,lj,b] = tanh( sum_m A[row(m),b] * W[loc,o,m] + bias[loc,o] )
// Thread tile: 4 sample-pairs (f32x2) x 8 outputs.
template<int CIN, int HIN, int KH, int KW, int COUT, int HOUT,
         int COUT_TILE, int SAMPLES, int KT, int THREADS, int MINB>
__global__ void __launch_bounds__(THREADS, MINB)
lc_layer(const float* __restrict__ A, const float* __restrict__ Wt,
         const float* __restrict__ bias, float* __restrict__ Out)
{
    constexpr int K   = CIN * KH * KW;
    constexpr int TMP = 4;                 // sample pairs per thread
    constexpr int TN  = 8;                 // outputs per thread
    constexpr int PG  = SAMPLES / 2 / TMP; // threads along batch
    constexpr int OG  = COUT_TILE / TN;    // threads along outputs
    constexpr int RL  = COUT_TILE + 2;     // padded W row (u64), 16B-aligned rows
    static_assert(PG * OG == THREADS, "thread decomposition");
    static_assert(K % KT == 0, "K tiling");

    const int loc   = blockIdx.y;
    const int li    = loc / HOUT;
    const int lj    = loc % HOUT;
    const int b0    = blockIdx.x * SAMPLES;
    const int obase = blockIdx.z * COUT_TILE;

    __shared__ __align__(16) float sA[KT][SAMPLES];
    __shared__ __align__(16) u64   sW[KT * RL];     // [kk][o], duplicated {w,w}

    const int tid = threadIdx.x;
    const int tpx = tid % PG;
    const int tpy = tid / PG;

    u64 acc[TMP][TN];
    #pragma unroll
    for (int m = 0; m < TMP; m++)
        #pragma unroll
        for (int n = 0; n < TN; n++) acc[m][n] = 0ull;

    const float* Wloc = Wt + ((size_t)loc * COUT + obase) * K;

    for (int kt = 0; kt < K; kt += KT) {
        // --- stage A tile (coalesced float4, b-fastest layout) ---
        for (int idx = tid; idx < KT * SAMPLES / 4; idx += THREADS) {
            const int kk = idx / (SAMPLES / 4);
            const int s4 = idx % (SAMPLES / 4);
            const int m  = kt + kk;
            const int c  = m / (KH * KW);
            const int rm = m % (KH * KW);
            const int r  = rm / KW;
            const int l  = rm % KW;
            const int row = (c * HIN + li * KH + r) * HIN + (lj * KW + l);
            *(float4*)&sA[kk][s4 * 4] =
                *(const float4*)(A + (size_t)row * BATCH + b0 + s4 * 4);
        }
        // --- stage W tile into [kk][o], duplicated into both f32x2 lanes ---
        if constexpr ((K % 4 == 0) && (KT % 4 == 0)) {
            // vectorized, coalesced along k
            for (int idx = tid; idx < COUT_TILE * KT / 4; idx += THREADS) {
                const int o  = idx / (KT / 4);
                const int k4 = idx % (KT / 4);
                const float4 wv =
                    *(const float4*)(Wloc + (size_t)o * K + kt + k4 * 4);
                const unsigned ux = __float_as_uint(wv.x);
                const unsigned uy = __float_as_uint(wv.y);
                const unsigned uz = __float_as_uint(wv.z);
                const unsigned uw = __float_as_uint(wv.w);
                sW[(k4 * 4 + 0) * RL + o] = ((u64)ux << 32) | ux;
                sW[(k4 * 4 + 1) * RL + o] = ((u64)uy << 32) | uy;
                sW[(k4 * 4 + 2) * RL + o] = ((u64)uz << 32) | uz;
                sW[(k4 * 4 + 3) * RL + o] = ((u64)uw << 32) | uw;
            }
        } else {
            for (int idx = tid; idx < COUT_TILE * KT; idx += THREADS) {
                const int o  = idx / KT;
                const int kk = idx % KT;
                const unsigned ub =
                    __float_as_uint(Wloc[(size_t)o * K + kt + kk]);
                sW[kk * RL + o] = ((u64)ub << 32) | ub;
            }
        }
        __syncthreads();

        #pragma unroll 4
        for (int kk = 0; kk < KT; kk++) {
            const u64* sa = (const u64*)sA[kk];
            const ulonglong2 a01 = *(const ulonglong2*)&sa[tpx * TMP];
            const ulonglong2 a23 = *(const ulonglong2*)&sa[tpx * TMP + 2];
            const u64 a[TMP] = {a01.x, a01.y, a23.x, a23.y};

            const u64* wr = &sW[kk * RL + tpy * TN];
            u64 w[TN];
            #pragma unroll
            for (int n = 0; n < TN; n += 2) {
                const ulonglong2 wp = *(const ulonglong2*)&wr[n];
                w[n] = wp.x; w[n + 1] = wp.y;
            }
            #pragma unroll
            for (int m = 0; m < TMP; m++)
                #pragma unroll
                for (int n = 0; n < TN; n++)
                    acc[m][n] = ffma2(a[m], w[n], acc[m][n]);
        }
        __syncthreads();
    }

    // --- epilogue: bias + tanh, store [o, li, lj, b] (float4 x2 per row) ---
    #pragma unroll
    for (int n = 0; n < TN; n++) {
        const int o  = obase + tpy * TN + n;
        const float bv = bias[loc * COUT + o];
        float v[2 * TMP];
        #pragma unroll
        for (int m = 0; m < TMP; m++) {
            v[2 * m + 0] = tanh_fast(
                __uint_as_float((unsigned)(acc[m][n] & 0xffffffffu)) + bv);
            v[2 * m + 1] = tanh_fast(
                __uint_as_float((unsigned)(acc[m][n] >> 32)) + bv);
        }
        float* dst = Out + (((size_t)o * HOUT + li) * HOUT + lj) * BATCH
                         + b0 + tpx * (2 * TMP);
        *(float4*)(dst + 0) = make_float4(v[0], v[1], v[2], v[3]);
        *(float4*)(dst + 4) = make_float4(v[4], v[5], v[6], v[7]);
    }
}

// ------------------------- classifier + softmax ----------------------------
__global__ void __launch_bounds__(256)
classifier_kernel(const float* __restrict__ h2,    // [512, B]
                  const float* __restrict__ info,  // [B, 2]
                  const float* __restrict__ Wc,    // [514, 2]
                  const float* __restrict__ bc,    // [2]
                  float* __restrict__ out)         // [B, 2]
{
    __shared__ float sW[514 * 2];
    const int tid = threadIdx.x;
    for (int i = tid; i < 514 * 2; i += 256) sW[i] = Wc[i];
    __syncthreads();

    const int b = blockIdx.x * 256 + tid;
    float l0 = bc[0], l1 = bc[1];
    #pragma unroll 8
    for (int f = 0; f < 512; f++) {
        const float v = h2[(size_t)f * BATCH + b];
        l0 = fmaf(v, sW[f * 2 + 0], l0);
        l1 = fmaf(v, sW[f * 2 + 1], l1);
    }
    const float2 iv = *(const float2*)(info + (size_t)b * 2);
    l0 = fmaf(iv.x, sW[512 * 2 + 0], fmaf(iv.y, sW[513 * 2 + 0], l0));
    l1 = fmaf(iv.x, sW[512 * 2 + 1], fmaf(iv.y, sW[513 * 2 + 1], l1));

    const float mx = fmaxf(l0, l1);
    const float e0 = __expf(l0 - mx);
    const float e1 = __expf(l1 - mx);
    const float inv = 1.0f / (e0 + e1);
    *(float2*)(out + (size_t)b * 2) = make_float2(e0 * inv, e1 * inv);
}

// ---------------------------------------------------------------------------
extern "C" void kernel_launch(void* const* d_in, const int* in_sizes, int n_in,
                              void* d_out, int out_size) {
    const float* x    = (const float*)d_in[0];
    const float* info = (const float*)d_in[1];
    const float* W0   = (const float*)d_in[2];
    const float* B0   = (const float*)d_in[3];
    const float* W1   = (const float*)d_in[4];
    const float* B1   = (const float*)d_in[5];
    const float* W2   = (const float*)d_in[6];
    const float* B2   = (const float*)d_in[7];
    const float* Wc   = (const float*)d_in[8];
    const float* bc   = (const float*)d_in[9];
    float* out = (float*)d_out;

    float *xT, *h0, *h1, *h2;
    cudaGetSymbolAddress((void**)&xT, g_xT);
    cudaGetSymbolAddress((void**)&h0, g_h0);
    cudaGetSymbolAddress((void**)&h1, g_h1);
    cudaGetSymbolAddress((void**)&h2, g_h2);

    // 1) x [B,21600] -> xT [21600,B]
    transpose_kernel<<<dim3(21600 / 32, BATCH / 32), dim3(32, 8)>>>(x, xT);

    // 2) L0: 6x60x60 -> 32x20x20, k=3 (K=54).  400 loc.
    //    COUT_TILE=32, SAMPLES=256, KT=27, 128 thr, 4 blk/SM. grid=6400.
    lc_layer<6, 60, 3, 3, 32, 20,   32, 256, 27, 128, 4>
        <<<dim3(BATCH / 256, 400, 1), 128>>>(xT, W0, B0, h0);

    // 3) L1: 32x20x20 -> 64x10x10, k=2 (K=128). 100 loc.
    //    COUT_TILE=64, SAMPLES=256, KT=16, 256 thr, 2 blk/SM. grid=1600.
    lc_layer<32, 20, 2, 2, 64, 10,  64, 256, 16, 256, 2>
        <<<dim3(BATCH / 256, 100, 1), 256>>>(h0, W1, B1, h1);

    // 4) L2: 64x10x10 -> 128x2x2, k=5 (K=1600). 4 loc, Cout split x2.
    //    COUT_TILE=64, SAMPLES=64, KT=32, 64 thr, 8 blk/SM. grid=512.
    lc_layer<64, 10, 5, 5, 128, 2,  64, 64, 32, 64, 8>
        <<<dim3(BATCH / 64, 4, 2), 64>>>(h1, W2, B2, h2);

    // 5) classifier + softmax
    classifier_kernel<<<BATCH / 256, 256>>>(h2, info, Wc, bc, out);
}

// round 6
// speedup vs baseline: 1.0751x; 1.0006x over previous
#include <cuda_runtime.h>
#include <math.h>

// ---------------------------------------------------------------------------
// resCNN: 3 locally-connected conv layers (kernel==stride) + tanh,
//         Linear(514,2) + softmax. B = 4096.
//
// Layout: x transposed once to [CHW, B]; intermediates [Cout,i,j,B].
// Each LC layer = per-location GEMM [B x K] x [K x Cout], fp32 with packed
// fma.rn.f32x2 (2 samples / 64-bit reg) at 128 FMA/cyc/SM.
// Micro-tile 4 sample-pairs x 8 outputs per thread: 32 ffma2 per k-step vs
// ~1.1KB smem traffic/warp -> fma-pipe bound (prev version was LDS-bound 2:1).
// ---------------------------------------------------------------------------

#define BATCH 4096

using u64 = unsigned long long;

// Scratch (device globals — no allocations allowed in kernel_launch)
__device__ float g_xT[21600u * BATCH];           // [6*60*60, B]
__device__ float g_h0[32u * 20 * 20 * BATCH];    // [32,20,20,B]
__device__ float g_h1[64u * 10 * 10 * BATCH];    // [64,10,10,B]
__device__ float g_h2[512u * BATCH];             // [512, B]

__device__ __forceinline__ u64 ffma2(u64 a, u64 b, u64 c) {
    u64 d;
    asm("fma.rn.f32x2 %0, %1, %2, %3;" : "=l"(d) : "l"(a), "l"(b), "l"(c));
    return d;
}

// tanh(x) = 1 - 2/(exp(2x)+1); MUFU.EX2 + MUFU.RCP path, abs err ~1e-7.
__device__ __forceinline__ float tanh_fast(float x) {
    float e = __expf(2.0f * x);
    return 1.0f - __fdividef(2.0f, e + 1.0f);
}

// ------------------------- transpose: [B,CHW] -> [CHW,B] -------------------
__global__ void transpose_kernel(const float* __restrict__ in,
                                 float* __restrict__ out) {
    __shared__ float tile[32][33];
    const int bx = blockIdx.x * 32;   // chw base
    const int by = blockIdx.y * 32;   // batch base
    const int tx = threadIdx.x;
    const int ty = threadIdx.y;
    #pragma unroll
    for (int r = 0; r < 32; r += 8)
        tile[ty + r][tx] = in[(size_t)(by + ty + r) * 21600 + (bx + tx)];
    __syncthreads();
    #pragma unroll
    for (int r = 0; r < 32; r += 8)
        out[(size_t)(bx + ty + r) * BATCH + (by + tx)] = tile[tx][ty + r];
}

// ------------------------- locally connected layer -------------------------
// Out[o,li,lj,b] = tanh( sum_m A[row(m),b] * W[loc,o,m] + bias[loc,o] )
// Thread tile: 4 sample-pairs (f32x2) x 8 outputs.
template<int CIN, int HIN, int KH, int KW, int COUT, int HOUT,
         int COUT_TILE, int SAMPLES, int KT, int THREADS, int MINB>
__global__ void __launch_bounds__(THREADS, MINB)
lc_layer(const float* __restrict__ A, const float* __restrict__ Wt,
         const float* __restrict__ bias, float* __restrict__ Out)
{
    constexpr int K   = CIN * KH * KW;
    constexpr int TMP = 4;                 // sample pairs per thread
    constexpr int TN  = 8;                 // outputs per thread
    constexpr int PG  = SAMPLES / 2 / TMP; // threads along batch
    constexpr int OG  = COUT_TILE / TN;    // threads along outputs
    constexpr int RL  = COUT_TILE + 2;     // padded W row (u64), 16B-aligned rows
    static_assert(PG * OG == THREADS, "thread decomposition");
    static_assert(K % KT == 0, "K tiling");

    const int loc   = blockIdx.y;
    const int li    = loc / HOUT;
    const int lj    = loc % HOUT;
    const int b0    = blockIdx.x * SAMPLES;
    const int obase = blockIdx.z * COUT_TILE;

    __shared__ __align__(16) float sA[KT][SAMPLES];
    __shared__ __align__(16) u64   sW[KT * RL];     // [kk][o], duplicated {w,w}

    const int tid = threadIdx.x;
    const int tpx = tid % PG;
    const int tpy = tid / PG;

    u64 acc[TMP][TN];
    #pragma unroll
    for (int m = 0; m < TMP; m++)
        #pragma unroll
        for (int n = 0; n < TN; n++) acc[m][n] = 0ull;

    const float* Wloc = Wt + ((size_t)loc * COUT + obase) * K;

    for (int kt = 0; kt < K; kt += KT) {
        // --- stage A tile (coalesced float4, b-fastest layout) ---
        for (int idx = tid; idx < KT * SAMPLES / 4; idx += THREADS) {
            const int kk = idx / (SAMPLES / 4);
            const int s4 = idx % (SAMPLES / 4);
            const int m  = kt + kk;
            const int c  = m / (KH * KW);
            const int rm = m % (KH * KW);
            const int r  = rm / KW;
            const int l  = rm % KW;
            const int row = (c * HIN + li * KH + r) * HIN + (lj * KW + l);
            *(float4*)&sA[kk][s4 * 4] =
                *(const float4*)(A + (size_t)row * BATCH + b0 + s4 * 4);
        }
        // --- stage W tile into [kk][o], duplicated into both f32x2 lanes ---
        if constexpr ((K % 4 == 0) && (KT % 4 == 0)) {
            // vectorized, coalesced along k
            for (int idx = tid; idx < COUT_TILE * KT / 4; idx += THREADS) {
                const int o  = idx / (KT / 4);
                const int k4 = idx % (KT / 4);
                const float4 wv =
                    *(const float4*)(Wloc + (size_t)o * K + kt + k4 * 4);
                const unsigned ux = __float_as_uint(wv.x);
                const unsigned uy = __float_as_uint(wv.y);
                const unsigned uz = __float_as_uint(wv.z);
                const unsigned uw = __float_as_uint(wv.w);
                sW[(k4 * 4 + 0) * RL + o] = ((u64)ux << 32) | ux;
                sW[(k4 * 4 + 1) * RL + o] = ((u64)uy << 32) | uy;
                sW[(k4 * 4 + 2) * RL + o] = ((u64)uz << 32) | uz;
                sW[(k4 * 4 + 3) * RL + o] = ((u64)uw << 32) | uw;
            }
        } else {
            for (int idx = tid; idx < COUT_TILE * KT; idx += THREADS) {
                const int o  = idx / KT;
                const int kk = idx % KT;
                const unsigned ub =
                    __float_as_uint(Wloc[(size_t)o * K + kt + kk]);
                sW[kk * RL + o] = ((u64)ub << 32) | ub;
            }
        }
        __syncthreads();

        #pragma unroll 4
        for (int kk = 0; kk < KT; kk++) {
            const u64* sa = (const u64*)sA[kk];
            const ulonglong2 a01 = *(const ulonglong2*)&sa[tpx * TMP];
            const ulonglong2 a23 = *(const ulonglong2*)&sa[tpx * TMP + 2];
            const u64 a[TMP] = {a01.x, a01.y, a23.x, a23.y};

            const u64* wr = &sW[kk * RL + tpy * TN];
            u64 w[TN];
            #pragma unroll
            for (int n = 0; n < TN; n += 2) {
                const ulonglong2 wp = *(const ulonglong2*)&wr[n];
                w[n] = wp.x; w[n + 1] = wp.y;
            }
            #pragma unroll
            for (int m = 0; m < TMP; m++)
                #pragma unroll
                for (int n = 0; n < TN; n++)
                    acc[m][n] = ffma2(a[m], w[n], acc[m][n]);
        }
        __syncthreads();
    }

    // --- epilogue: bias + tanh, store [o, li, lj, b] (float4 x2 per row) ---
    #pragma unroll
    for (int n = 0; n < TN; n++) {
        const int o  = obase + tpy * TN + n;
        const float bv = bias[loc * COUT + o];
        float v[2 * TMP];
        #pragma unroll
        for (int m = 0; m < TMP; m++) {
            v[2 * m + 0] = tanh_fast(
                __uint_as_float((unsigned)(acc[m][n] & 0xffffffffu)) + bv);
            v[2 * m + 1] = tanh_fast(
                __uint_as_float((unsigned)(acc[m][n] >> 32)) + bv);
        }
        float* dst = Out + (((size_t)o * HOUT + li) * HOUT + lj) * BATCH
                         + b0 + tpx * (2 * TMP);
        *(float4*)(dst + 0) = make_float4(v[0], v[1], v[2], v[3]);
        *(float4*)(dst + 4) = make_float4(v[4], v[5], v[6], v[7]);
    }
}

// ------------------------- classifier + softmax ----------------------------
__global__ void __launch_bounds__(256)
classifier_kernel(const float* __restrict__ h2,    // [512, B]
                  const float* __restrict__ info,  // [B, 2]
                  const float* __restrict__ Wc,    // [514, 2]
                  const float* __restrict__ bc,    // [2]
                  float* __restrict__ out)         // [B, 2]
{
    __shared__ float sW[514 * 2];
    const int tid = threadIdx.x;
    for (int i = tid; i < 514 * 2; i += 256) sW[i] = Wc[i];
    __syncthreads();

    const int b = blockIdx.x * 256 + tid;
    float l0 = bc[0], l1 = bc[1];
    #pragma unroll 8
    for (int f = 0; f < 512; f++) {
        const float v = h2[(size_t)f * BATCH + b];
        l0 = fmaf(v, sW[f * 2 + 0], l0);
        l1 = fmaf(v, sW[f * 2 + 1], l1);
    }
    const float2 iv = *(const float2*)(info + (size_t)b * 2);
    l0 = fmaf(iv.x, sW[512 * 2 + 0], fmaf(iv.y, sW[513 * 2 + 0], l0));
    l1 = fmaf(iv.x, sW[512 * 2 + 1], fmaf(iv.y, sW[513 * 2 + 1], l1));

    const float mx = fmaxf(l0, l1);
    const float e0 = __expf(l0 - mx);
    const float e1 = __expf(l1 - mx);
    const float inv = 1.0f / (e0 + e1);
    *(float2*)(out + (size_t)b * 2) = make_float2(e0 * inv, e1 * inv);
}

// ---------------------------------------------------------------------------
extern "C" void kernel_launch(void* const* d_in, const int* in_sizes, int n_in,
                              void* d_out, int out_size) {
    const float* x    = (const float*)d_in[0];
    const float* info = (const float*)d_in[1];
    const float* W0   = (const float*)d_in[2];
    const float* B0   = (const float*)d_in[3];
    const float* W1   = (const float*)d_in[4];
    const float* B1   = (const float*)d_in[5];
    const float* W2   = (const float*)d_in[6];
    const float* B2   = (const float*)d_in[7];
    const float* Wc   = (const float*)d_in[8];
    const float* bc   = (const float*)d_in[9];
    float* out = (float*)d_out;

    float *xT, *h0, *h1, *h2;
    cudaGetSymbolAddress((void**)&xT, g_xT);
    cudaGetSymbolAddress((void**)&h0, g_h0);
    cudaGetSymbolAddress((void**)&h1, g_h1);
    cudaGetSymbolAddress((void**)&h2, g_h2);

    // 1) x [B,21600] -> xT [21600,B]
    transpose_kernel<<<dim3(21600 / 32, BATCH / 32), dim3(32, 8)>>>(x, xT);

    // 2) L0: 6x60x60 -> 32x20x20, k=3 (K=54).  400 loc.
    //    COUT_TILE=32, SAMPLES=256, KT=27, 128 thr, 4 blk/SM. grid=6400.
    lc_layer<6, 60, 3, 3, 32, 20,   32, 256, 27, 128, 4>
        <<<dim3(BATCH / 256, 400, 1), 128>>>(xT, W0, B0, h0);

    // 3) L1: 32x20x20 -> 64x10x10, k=2 (K=128). 100 loc.
    //    COUT_TILE=64, SAMPLES=256, KT=16, 256 thr, 2 blk/SM. grid=1600.
    lc_layer<32, 20, 2, 2, 64, 10,  64, 256, 16, 256, 2>
        <<<dim3(BATCH / 256, 100, 1), 256>>>(h0, W1, B1, h1);

    // 4) L2: 64x10x10 -> 128x2x2, k=5 (K=1600). 4 loc, Cout split x2.
    //    COUT_TILE=64, SAMPLES=64, KT=32, 64 thr, 8 blk/SM. grid=512.
    lc_layer<64, 10, 5, 5, 128, 2,  64, 64, 32, 64, 8>
        <<<dim3(BATCH / 64, 4, 2), 64>>>(h1, W2, B2, h2);

    // 5) classifier + softmax
    classifier_kernel<<<BATCH / 256, 256>>>(h2, info, Wc, bc, out);
}